// round 2
// baseline (speedup 1.0000x reference)
#include <cuda_runtime.h>
#include <cuda_bf16.h>
#include <math_constants.h>

// Problem constants
constexpr int B  = 2;
constexpr int T  = 2048;
constexpr int D  = 2048;
constexpr int H  = 32;
constexpr int HD = 64;
constexpr int M  = B * T;      // 4096 rows for GEMMs
constexpr int N  = D;          // 2048
constexpr int K  = D;          // 2048

// Scratch (device globals: allocation-free rule)
__device__ float g_q[(size_t)B * H * T * HD];    // [B,H,T,HD]
__device__ float g_k[(size_t)B * H * T * HD];
__device__ float g_v[(size_t)B * H * T * HD];
__device__ float g_ctx[(size_t)B * T * D];       // [B,T,D]

// ---------------------------------------------------------------------------
// GEMM: out = A[M,K] @ W[N,K]^T + bias[N]
// MODE 0/1/2 : write q/k/v in [B,H,T,HD] layout,  A = A_in
// MODE 3     : write flat [M,N] to out_p,         A = g_ctx
// Tiling: 128x128x16, 256 threads, 8x8 per-thread microtile.
// Double-buffered smem + register-staged global prefetch:
//   while FFMAs run on buf[cur], next K-tile sits in registers and is stored
//   to buf[cur^1]; one __syncthreads per K-step.
// ---------------------------------------------------------------------------
template<int MODE>
__global__ __launch_bounds__(256)
void gemm_k(const float* __restrict__ A_in, const float* __restrict__ W,
            const float* __restrict__ bias, float* __restrict__ out_p)
{
    __shared__ float As[2][16][128];   // [buf][k][m] transposed
    __shared__ float Bs[2][16][128];   // [buf][k][n] transposed

    const float* A = (MODE < 3) ? A_in : g_ctx;

    const int tid = threadIdx.x;
    const int tx  = tid & 15;       // 0..15  -> n microtile
    const int ty  = tid >> 4;       // 0..15  -> m microtile
    const int m0  = blockIdx.y * 128;
    const int n0  = blockIdx.x * 128;

    // Per-thread load coordinates (2 float4 per operand per K-step)
    const int r_ld[2]  = { tid >> 1, (tid + 256) >> 1 };        // rows 0..127, covers 128 rows twice? no:
    // tid in [0,256): idx0 = tid -> r = tid>>2? -- keep original mapping:
    // idx = tid + i*256; r = idx>>2 (0..127); kq = (idx&3)<<2 (0,4,8,12)

    float acc[8][8];
#pragma unroll
    for (int i = 0; i < 8; i++)
#pragma unroll
        for (int j = 0; j < 8; j++) acc[i][j] = 0.0f;

    // ---- prologue: load K-tile 0 into regs, store to buf 0 ----
    float4 pa[2], pb[2];
#pragma unroll
    for (int i = 0; i < 2; i++) {
        const int idx = tid + i * 256;
        const int r   = idx >> 2;
        const int kq  = (idx & 3) << 2;
        pa[i] = *(const float4*)&A[(size_t)(m0 + r) * K + kq];
        pb[i] = *(const float4*)&W[(size_t)(n0 + r) * K + kq];
    }
#pragma unroll
    for (int i = 0; i < 2; i++) {
        const int idx = tid + i * 256;
        const int r   = idx >> 2;
        const int kq  = (idx & 3) << 2;
        As[0][kq + 0][r] = pa[i].x; As[0][kq + 1][r] = pa[i].y;
        As[0][kq + 2][r] = pa[i].z; As[0][kq + 3][r] = pa[i].w;
        Bs[0][kq + 0][r] = pb[i].x; Bs[0][kq + 1][r] = pb[i].y;
        Bs[0][kq + 2][r] = pb[i].z; Bs[0][kq + 3][r] = pb[i].w;
    }
    __syncthreads();

    int cur = 0;
    for (int k0 = 0; k0 < K; k0 += 16) {
        const bool has_next = (k0 + 16) < K;

        // issue next tile's global loads early (latency overlapped with FFMAs)
        if (has_next) {
#pragma unroll
            for (int i = 0; i < 2; i++) {
                const int idx = tid + i * 256;
                const int r   = idx >> 2;
                const int kq  = (idx & 3) << 2;
                pa[i] = *(const float4*)&A[(size_t)(m0 + r) * K + k0 + 16 + kq];
                pb[i] = *(const float4*)&W[(size_t)(n0 + r) * K + k0 + 16 + kq];
            }
        }

        // compute on buf[cur]
#pragma unroll
        for (int kk = 0; kk < 16; kk++) {
            float a[8], b[8];
            *(float4*)&a[0] = *(const float4*)&As[cur][kk][ty * 8];
            *(float4*)&a[4] = *(const float4*)&As[cur][kk][ty * 8 + 4];
            *(float4*)&b[0] = *(const float4*)&Bs[cur][kk][tx * 8];
            *(float4*)&b[4] = *(const float4*)&Bs[cur][kk][tx * 8 + 4];
#pragma unroll
            for (int i = 0; i < 8; i++)
#pragma unroll
                for (int j = 0; j < 8; j++)
                    acc[i][j] = fmaf(a[i], b[j], acc[i][j]);
        }

        // store staged regs to the other buffer (nobody reads it this iter)
        if (has_next) {
            const int nxt = cur ^ 1;
#pragma unroll
            for (int i = 0; i < 2; i++) {
                const int idx = tid + i * 256;
                const int r   = idx >> 2;
                const int kq  = (idx & 3) << 2;
                As[nxt][kq + 0][r] = pa[i].x; As[nxt][kq + 1][r] = pa[i].y;
                As[nxt][kq + 2][r] = pa[i].z; As[nxt][kq + 3][r] = pa[i].w;
                Bs[nxt][kq + 0][r] = pb[i].x; Bs[nxt][kq + 1][r] = pb[i].y;
                Bs[nxt][kq + 2][r] = pb[i].z; Bs[nxt][kq + 3][r] = pb[i].w;
            }
            __syncthreads();
            cur = nxt;
        }
    }

    // bias
    float bb[8];
    *(float4*)&bb[0] = *(const float4*)&bias[n0 + tx * 8];
    *(float4*)&bb[4] = *(const float4*)&bias[n0 + tx * 8 + 4];

#pragma unroll
    for (int i = 0; i < 8; i++) {
        const int m = m0 + ty * 8 + i;
        float4 o0 = make_float4(acc[i][0] + bb[0], acc[i][1] + bb[1],
                                acc[i][2] + bb[2], acc[i][3] + bb[3]);
        float4 o1 = make_float4(acc[i][4] + bb[4], acc[i][5] + bb[5],
                                acc[i][6] + bb[6], acc[i][7] + bb[7]);
        if (MODE == 3) {
            float* dst = out_p + (size_t)m * N + n0 + tx * 8;
            *(float4*)dst       = o0;
            *(float4*)(dst + 4) = o1;
        } else {
            // [B,H,T,HD] layout. n..n+7 stay inside one head (8 | 64).
            const int bb_i = m >> 11;          // m / T
            const int t    = m & (T - 1);
            const int n    = n0 + tx * 8;
            const int h    = n >> 6;           // n / HD
            const int hd   = n & (HD - 1);
            float* base = (MODE == 0) ? g_q : (MODE == 1) ? g_k : g_v;
            float* dst = base + (((size_t)(bb_i * H + h) * T + t) * HD + hd);
            *(float4*)dst       = o0;
            *(float4*)(dst + 4) = o1;
        }
    }
}

// ---------------------------------------------------------------------------
// Flash attention (causal), BM=BN=64, HD=64.
// 256 threads = 8 warps; warp w owns query rows w*8..w*8+7.
// Lane l owns output columns {l, l+32}.
// K^T stored XOR-swizzled in sKP; sKP reused as P tile after scores.
// Static smem: 3 * 16KB = 48KB exactly.
// ---------------------------------------------------------------------------
constexpr int BM = 64;
constexpr int BN = 64;

__device__ __forceinline__ int kt_idx(int d, int c) {
    return d * 64 + (c ^ (d & 31));
}

__global__ __launch_bounds__(256)
void attn_kernel()
{
    __shared__ float sQ[BM * HD];
    __shared__ float sKP[BN * HD];   // K^T (swizzled) then P (plain [r][c])
    __shared__ float sV[BN * HD];

    const int tid  = threadIdx.x;
    const int warp = tid >> 5;
    const int lane = tid & 31;
    const int bh   = blockIdx.y;          // 0..B*H-1
    const int b    = bh >> 5;
    const int h    = bh & (H - 1);
    const int q0   = blockIdx.x * BM;

    const float* qb = g_q + (size_t)bh * T * HD;
    const float* kb = g_k + (size_t)bh * T * HD;
    const float* vb = g_v + (size_t)bh * T * HD;

    // Load Q tile ([t][hd] contiguous -> coalesced)
#pragma unroll
    for (int i = 0; i < (BM * HD) / 256; i++)
        sQ[tid + i * 256] = qb[(size_t)q0 * HD + tid + i * 256];

    const int r0 = warp * 8;
    const int c1 = lane, c2 = lane + 32;

    float acc[8][2];
    float mrow[8], lrow[8];
#pragma unroll
    for (int r = 0; r < 8; r++) {
        acc[r][0] = 0.0f; acc[r][1] = 0.0f;
        mrow[r] = -CUDART_INF_F; lrow[r] = 0.0f;
    }

    for (int j0 = 0; j0 <= q0; j0 += BN) {
        __syncthreads();  // prior P/V reads done (also covers Q load on iter 0)

        // Load K (transposed+swizzled) and V
#pragma unroll
        for (int i = 0; i < (BN * HD) / 256; i++) {
            const int idx = tid + i * 256;
            const int c = idx >> 6;            // key row in tile
            const int d = idx & 63;            // head dim
            sKP[kt_idx(d, c)] = kb[(size_t)j0 * HD + idx];
            sV[idx]           = vb[(size_t)j0 * HD + idx];
        }
        __syncthreads();

        // Scores S[r][c1], S[r][c2]
        float s1[8], s2[8];
#pragma unroll
        for (int r = 0; r < 8; r++) { s1[r] = 0.0f; s2[r] = 0.0f; }

#pragma unroll
        for (int d4 = 0; d4 < HD; d4 += 4) {
            float k1[4], k2[4];
#pragma unroll
            for (int u = 0; u < 4; u++) {
                const int d = d4 + u;
                k1[u] = sKP[kt_idx(d, c1)];
                k2[u] = sKP[kt_idx(d, c2)];
            }
#pragma unroll
            for (int r = 0; r < 8; r++) {
                float4 qv = *(const float4*)&sQ[(r0 + r) * 64 + d4];
                s1[r] = fmaf(qv.x, k1[0], fmaf(qv.y, k1[1], fmaf(qv.z, k1[2], fmaf(qv.w, k1[3], s1[r]))));
                s2[r] = fmaf(qv.x, k2[0], fmaf(qv.y, k2[1], fmaf(qv.z, k2[2], fmaf(qv.w, k2[3], s2[r]))));
            }
        }

        const bool diag = (j0 == q0);
        float p1[8], p2[8];
#pragma unroll
        for (int r = 0; r < 8; r++) {
            s1[r] *= 0.125f;                       // 1/sqrt(64)
            s2[r] *= 0.125f;
            if (diag) {
                const int rg = q0 + r0 + r;
                if (j0 + c1 > rg) s1[r] = -CUDART_INF_F;
                if (j0 + c2 > rg) s2[r] = -CUDART_INF_F;
            }
            // online softmax update
            float mt = fmaxf(s1[r], s2[r]);
#pragma unroll
            for (int o = 16; o > 0; o >>= 1)
                mt = fmaxf(mt, __shfl_xor_sync(0xffffffffu, mt, o));
            const float mnew = fmaxf(mrow[r], mt);
            const float resc = __expf(mrow[r] - mnew);   // exp(-inf)=0 on first tile
            p1[r] = __expf(s1[r] - mnew);
            p2[r] = __expf(s2[r] - mnew);
            float ps = p1[r] + p2[r];
#pragma unroll
            for (int o = 16; o > 0; o >>= 1)
                ps += __shfl_xor_sync(0xffffffffu, ps, o);
            lrow[r] = lrow[r] * resc + ps;
            mrow[r] = mnew;
            acc[r][0] *= resc;
            acc[r][1] *= resc;
        }

        __syncthreads();  // every warp done reading K from sKP

        // Write P (plain layout); only this warp reads its own rows back
#pragma unroll
        for (int r = 0; r < 8; r++) {
            sKP[(r0 + r) * 64 + c1] = p1[r];
            sKP[(r0 + r) * 64 + c2] = p2[r];
        }
        __syncwarp();

        // O += P @ V
#pragma unroll
        for (int c4 = 0; c4 < BN; c4 += 4) {
            float v1[4], v2[4];
#pragma unroll
            for (int u = 0; u < 4; u++) {
                v1[u] = sV[(c4 + u) * 64 + c1];
                v2[u] = sV[(c4 + u) * 64 + c2];
            }
#pragma unroll
            for (int r = 0; r < 8; r++) {
                float4 pv = *(const float4*)&sKP[(r0 + r) * 64 + c4];
                acc[r][0] = fmaf(pv.x, v1[0], fmaf(pv.y, v1[1], fmaf(pv.z, v1[2], fmaf(pv.w, v1[3], acc[r][0]))));
                acc[r][1] = fmaf(pv.x, v2[0], fmaf(pv.y, v2[1], fmaf(pv.z, v2[2], fmaf(pv.w, v2[3], acc[r][1]))));
            }
        }
    }

    // Normalize + write ctx [B,T,D] at column h*HD
    float* cb = g_ctx + (size_t)b * T * D + (size_t)h * HD;
#pragma unroll
    for (int r = 0; r < 8; r++) {
        const float inv = 1.0f / lrow[r];
        const int t = q0 + r0 + r;
        cb[(size_t)t * D + c1] = acc[r][0] * inv;
        cb[(size_t)t * D + c2] = acc[r][1] * inv;
    }
}

// ---------------------------------------------------------------------------
// Launch
// ---------------------------------------------------------------------------
extern "C" void kernel_launch(void* const* d_in, const int* in_sizes, int n_in,
                              void* d_out, int out_size)
{
    const float* x  = (const float*)d_in[0];
    const float* Wq = (const float*)d_in[1];
    const float* bq = (const float*)d_in[2];
    const float* Wk = (const float*)d_in[3];
    const float* bk = (const float*)d_in[4];
    const float* Wv = (const float*)d_in[5];
    const float* bv = (const float*)d_in[6];
    const float* Wo = (const float*)d_in[7];
    const float* bo = (const float*)d_in[8];

    dim3 gg(N / 128, M / 128);   // (16, 32)
    gemm_k<0><<<gg, 256>>>(x, Wq, bq, nullptr);
    gemm_k<1><<<gg, 256>>>(x, Wk, bk, nullptr);
    gemm_k<2><<<gg, 256>>>(x, Wv, bv, nullptr);

    attn_kernel<<<dim3(T / BM, B * H), 256>>>();

    gemm_k<3><<<gg, 256>>>(nullptr, Wo, bo, (float*)d_out);
}

// round 5
// speedup vs baseline: 2.0677x; 2.0677x over previous
#include <cuda_runtime.h>
#include <cuda_bf16.h>
#include <math_constants.h>
#include <cstdint>

// Problem constants
constexpr int B  = 2;
constexpr int T  = 2048;
constexpr int D  = 2048;
constexpr int H  = 32;
constexpr int HD = 64;
constexpr int M  = B * T;      // 4096
constexpr int N  = D;          // 2048
constexpr int K  = D;          // 2048

// ---------------------------------------------------------------------------
// Device-global scratch (allocation-free rule)
// ---------------------------------------------------------------------------
__device__ float g_q[(size_t)B * H * T * HD];    // [B,H,T,HD]
__device__ float g_k[(size_t)B * H * T * HD];
__device__ float g_v[(size_t)B * H * T * HD];
__device__ float g_ctx[(size_t)B * T * D];       // [B,T,D]

__device__ __nv_bfloat16 g_xhi[(size_t)M * K];
__device__ __nv_bfloat16 g_xlo[(size_t)M * K];
__device__ __nv_bfloat16 g_chi[(size_t)M * K];
__device__ __nv_bfloat16 g_clo[(size_t)M * K];
__device__ __nv_bfloat16 g_whi[4][(size_t)N * K];
__device__ __nv_bfloat16 g_wlo[4][(size_t)N * K];

// ---------------------------------------------------------------------------
// PTX helpers (baseline sm_80/sm_90 features only — harness targets sm_100)
// ---------------------------------------------------------------------------
__device__ __forceinline__ uint32_t smem_u32(const void* p) {
    uint32_t a;
    asm("{ .reg .u64 t; cvta.to.shared.u64 t, %1; cvt.u32.u64 %0, t; }"
        : "=r"(a) : "l"(p));
    return a;
}

__device__ __forceinline__ void cp16(uint32_t d, const void* s) {
    asm volatile("cp.async.cg.shared.global [%0], [%1], 16;" :: "r"(d), "l"(s));
}
__device__ __forceinline__ void cp_commit()   { asm volatile("cp.async.commit_group;"); }
__device__ __forceinline__ void cp_wait1()    { asm volatile("cp.async.wait_group 1;"); }
__device__ __forceinline__ void cp_wait_all() { asm volatile("cp.async.wait_all;"); }

__device__ __forceinline__ void ldsm4(uint32_t* r, uint32_t addr) {
    asm volatile("ldmatrix.sync.aligned.m8n8.x4.shared.b16 {%0,%1,%2,%3}, [%4];"
                 : "=r"(r[0]), "=r"(r[1]), "=r"(r[2]), "=r"(r[3]) : "r"(addr));
}

__device__ __forceinline__ void mma16816(float* c, const uint32_t* a,
                                         const uint32_t* b) {
    asm volatile(
        "mma.sync.aligned.m16n8k16.row.col.f32.bf16.bf16.f32 "
        "{%0,%1,%2,%3}, {%4,%5,%6,%7}, {%8,%9}, {%0,%1,%2,%3};"
        : "+f"(c[0]), "+f"(c[1]), "+f"(c[2]), "+f"(c[3])
        : "r"(a[0]), "r"(a[1]), "r"(a[2]), "r"(a[3]), "r"(b[0]), "r"(b[1]));
}

// SW128 swizzle: byte offset within a 128-row x 128B tile
__device__ __forceinline__ uint32_t swz(int row, int col_bf16) {
    return (uint32_t)(row * 128 + ((((col_bf16 >> 3) ^ row) & 7) << 4) +
                      (col_bf16 & 7) * 2);
}

// ---------------------------------------------------------------------------
// Split fp32 -> bf16 hi/lo.  DST: 0=x, 1..4=W[DST-1], 5=ctx
// ---------------------------------------------------------------------------
template<int DST>
__global__ __launch_bounds__(256)
void split_k(const float* __restrict__ src_in, int n4)
{
    const int i = blockIdx.x * blockDim.x + threadIdx.x;
    if (i >= n4) return;
    const float* src = (DST == 5) ? (const float*)g_ctx : src_in;
    __nv_bfloat16* hp;
    __nv_bfloat16* lp;
    if (DST == 0)      { hp = g_xhi;        lp = g_xlo; }
    else if (DST == 5) { hp = g_chi;        lp = g_clo; }
    else               { hp = g_whi[DST-1]; lp = g_wlo[DST-1]; }

    float4 v = ((const float4*)src)[i];
    float a[4] = {v.x, v.y, v.z, v.w};
    __nv_bfloat16 h[4], l[4];
#pragma unroll
    for (int j = 0; j < 4; j++) {
        h[j] = __float2bfloat16(a[j]);
        l[j] = __float2bfloat16(a[j] - __bfloat162float(h[j]));
    }
    __nv_bfloat162* hp2 = (__nv_bfloat162*)hp;
    __nv_bfloat162* lp2 = (__nv_bfloat162*)lp;
    hp2[2*i]   = __nv_bfloat162(h[0], h[1]);
    hp2[2*i+1] = __nv_bfloat162(h[2], h[3]);
    lp2[2*i]   = __nv_bfloat162(l[0], l[1]);
    lp2[2*i+1] = __nv_bfloat162(l[2], l[3]);
}

// ---------------------------------------------------------------------------
// HMMA GEMM: out = A @ W^T + bias, bf16 hi+lo, 3-term compensation
// (Ahi*Bhi + Ahi*Blo + Alo*Bhi, fp32 accum; dropped lo*lo ~ 2^-18 rel).
// CTA 128x128, KC=64, cp.async double buffer, 8 warps (2x4), warp tile 64x32.
// MODE 0/1/2: A=x, W=Wq/Wk/Wv -> g_q/g_k/g_v [B,H,T,HD];  MODE 3: A=ctx -> flat
// ---------------------------------------------------------------------------
constexpr int KC    = 64;
constexpr int NSTG  = K / KC;             // 32
constexpr int TILEB = 128 * 128;          // 16 KB per operand tile
constexpr int STGB  = 4 * TILEB;          // 64 KB per stage
constexpr int SMEM_DYN = 2 * STGB;        // 128 KB

template<int MODE>
__global__ __launch_bounds__(256, 1)
void gemm_mma(const float* __restrict__ bias, float* __restrict__ out_p)
{
    extern __shared__ char smem[];
    const uint32_t sb = smem_u32(smem);
    const int tid  = threadIdx.x;
    const int warp = tid >> 5;
    const int lane = tid & 31;
    const int m0 = blockIdx.y * 128;
    const int n0 = blockIdx.x * 128;

    const __nv_bfloat16* Ahi = (MODE < 3) ? g_xhi : g_chi;
    const __nv_bfloat16* Alo = (MODE < 3) ? g_xlo : g_clo;
    const __nv_bfloat16* Bhi = g_whi[MODE < 3 ? MODE : 3];
    const __nv_bfloat16* Blo = g_wlo[MODE < 3 ? MODE : 3];

    const int wm = (warp >> 2) * 64;   // warp M base (0 or 64)
    const int wn = (warp & 3) * 32;    // warp N base

    float acc[4][4][4];
#pragma unroll
    for (int i = 0; i < 4; i++)
#pragma unroll
        for (int j = 0; j < 4; j++)
#pragma unroll
            for (int r = 0; r < 4; r++) acc[i][j][r] = 0.0f;

    auto issue_load = [&](int s) {
        const int k0 = s * KC;
        const uint32_t buf = sb + (s & 1) * STGB;
#pragma unroll
        for (int i = 0; i < 4; i++) {
            const int idx = tid + i * 256;       // 0..1023
            const int row = idx >> 3;            // 0..127
            const int ch  = idx & 7;             // 16B chunk
            const uint32_t off = row * 128 + (((ch ^ row) & 7) << 4);
            const size_t gA = (size_t)(m0 + row) * K + k0 + ch * 8;
            const size_t gB = (size_t)(n0 + row) * K + k0 + ch * 8;
            cp16(buf + 0 * TILEB + off, Ahi + gA);
            cp16(buf + 1 * TILEB + off, Alo + gA);
            cp16(buf + 2 * TILEB + off, Bhi + gB);
            cp16(buf + 3 * TILEB + off, Blo + gB);
        }
    };

    issue_load(0); cp_commit();
    issue_load(1); cp_commit();

    // fragment address components (ldmatrix x4 lane->8x8-matrix mapping)
    const int a_r = (lane & 7) + ((lane >> 3) & 1) * 8;   // m within 16
    const int a_c = ((lane >> 4) & 1) * 8;                // k within 16
    const int b_r = (lane & 7) + ((lane >> 4) & 1) * 8;   // n within 16
    const int b_c = ((lane >> 3) & 1) * 8;                // k within 16

    for (int s = 0; s < NSTG; s++) {
        cp_wait1();
        __syncthreads();
        const uint32_t buf = sb + (s & 1) * STGB;
        const uint32_t sAh = buf, sAl = buf + TILEB;
        const uint32_t sBh = buf + 2 * TILEB, sBl = buf + 3 * TILEB;

#pragma unroll
        for (int kk = 0; kk < 4; kk++) {
            const int kc = kk * 16;
            uint32_t ah[4][4], al[4][4], bh[2][4], bl[2][4];
#pragma unroll
            for (int mt = 0; mt < 4; mt++) {
                const uint32_t off = swz(wm + mt * 16 + a_r, kc + a_c);
                ldsm4(ah[mt], sAh + off);
                ldsm4(al[mt], sAl + off);
            }
#pragma unroll
            for (int np = 0; np < 2; np++) {
                const uint32_t off = swz(wn + np * 16 + b_r, kc + b_c);
                ldsm4(bh[np], sBh + off);
                ldsm4(bl[np], sBl + off);
            }
#pragma unroll
            for (int mt = 0; mt < 4; mt++)
#pragma unroll
                for (int nt = 0; nt < 4; nt++) {
                    const int np = nt >> 1, hb = (nt & 1) * 2;
                    mma16816(acc[mt][nt], ah[mt], &bh[np][hb]);
                    mma16816(acc[mt][nt], ah[mt], &bl[np][hb]);
                    mma16816(acc[mt][nt], al[mt], &bh[np][hb]);
                }
        }
        __syncthreads();
        if (s + 2 < NSTG) issue_load(s + 2);
        cp_commit();   // always commit so wait_group 1 stays exact
    }
    cp_wait_all();     // drain any tail empty groups

    // ---- epilogue: bias + store ----
    const int qr = lane >> 2;          // 0..7
    const int qc = (lane & 3) * 2;     // 0,2,4,6

#pragma unroll
    for (int mt = 0; mt < 4; mt++) {
#pragma unroll
        for (int nt = 0; nt < 4; nt++) {
            const int n  = n0 + wn + nt * 8 + qc;
            const float2 bb = *(const float2*)&bias[n];
            const int m_lo = m0 + wm + mt * 16 + qr;
            const int m_hi = m_lo + 8;

            float2 v0 = make_float2(acc[mt][nt][0] + bb.x, acc[mt][nt][1] + bb.y);
            float2 v1 = make_float2(acc[mt][nt][2] + bb.x, acc[mt][nt][3] + bb.y);

            if (MODE == 3) {
                *(float2*)&out_p[(size_t)m_lo * N + n] = v0;
                *(float2*)&out_p[(size_t)m_hi * N + n] = v1;
            } else {
                const int h  = n >> 6;
                const int hd = n & 63;
                float* base = (MODE == 0) ? g_q : (MODE == 1) ? g_k : g_v;
                const int b_lo = m_lo >> 11, t_lo = m_lo & (T - 1);
                const int b_hi = m_hi >> 11, t_hi = m_hi & (T - 1);
                *(float2*)&base[((size_t)(b_lo * H + h) * T + t_lo) * HD + hd] = v0;
                *(float2*)&base[((size_t)(b_hi * H + h) * T + t_hi) * HD + hd] = v1;
            }
        }
    }
}

// ---------------------------------------------------------------------------
// Flash attention (causal), BM=BN=64, HD=64 — unchanged from R2 pass.
// ---------------------------------------------------------------------------
constexpr int BM = 64;
constexpr int BN = 64;

__device__ __forceinline__ int kt_idx(int d, int c) {
    return d * 64 + (c ^ (d & 31));
}

__global__ __launch_bounds__(256)
void attn_kernel()
{
    __shared__ float sQ[BM * HD];
    __shared__ float sKP[BN * HD];
    __shared__ float sV[BN * HD];

    const int tid  = threadIdx.x;
    const int warp = tid >> 5;
    const int lane = tid & 31;
    const int bh   = blockIdx.y;
    const int b    = bh >> 5;
    const int h    = bh & (H - 1);
    const int q0   = blockIdx.x * BM;

    const float* qb = g_q + (size_t)bh * T * HD;
    const float* kb = g_k + (size_t)bh * T * HD;
    const float* vb = g_v + (size_t)bh * T * HD;

#pragma unroll
    for (int i = 0; i < (BM * HD) / 256; i++)
        sQ[tid + i * 256] = qb[(size_t)q0 * HD + tid + i * 256];

    const int r0 = warp * 8;
    const int c1 = lane, c2 = lane + 32;

    float acc[8][2];
    float mrow[8], lrow[8];
#pragma unroll
    for (int r = 0; r < 8; r++) {
        acc[r][0] = 0.0f; acc[r][1] = 0.0f;
        mrow[r] = -CUDART_INF_F; lrow[r] = 0.0f;
    }

    for (int j0 = 0; j0 <= q0; j0 += BN) {
        __syncthreads();

#pragma unroll
        for (int i = 0; i < (BN * HD) / 256; i++) {
            const int idx = tid + i * 256;
            const int c = idx >> 6;
            const int d = idx & 63;
            sKP[kt_idx(d, c)] = kb[(size_t)j0 * HD + idx];
            sV[idx]           = vb[(size_t)j0 * HD + idx];
        }
        __syncthreads();

        float s1[8], s2[8];
#pragma unroll
        for (int r = 0; r < 8; r++) { s1[r] = 0.0f; s2[r] = 0.0f; }

#pragma unroll
        for (int d4 = 0; d4 < HD; d4 += 4) {
            float k1[4], k2[4];
#pragma unroll
            for (int u = 0; u < 4; u++) {
                const int d = d4 + u;
                k1[u] = sKP[kt_idx(d, c1)];
                k2[u] = sKP[kt_idx(d, c2)];
            }
#pragma unroll
            for (int r = 0; r < 8; r++) {
                float4 qv = *(const float4*)&sQ[(r0 + r) * 64 + d4];
                s1[r] = fmaf(qv.x, k1[0], fmaf(qv.y, k1[1], fmaf(qv.z, k1[2], fmaf(qv.w, k1[3], s1[r]))));
                s2[r] = fmaf(qv.x, k2[0], fmaf(qv.y, k2[1], fmaf(qv.z, k2[2], fmaf(qv.w, k2[3], s2[r]))));
            }
        }

        const bool diag = (j0 == q0);
        float p1[8], p2[8];
#pragma unroll
        for (int r = 0; r < 8; r++) {
            s1[r] *= 0.125f;
            s2[r] *= 0.125f;
            if (diag) {
                const int rg = q0 + r0 + r;
                if (j0 + c1 > rg) s1[r] = -CUDART_INF_F;
                if (j0 + c2 > rg) s2[r] = -CUDART_INF_F;
            }
            float mt = fmaxf(s1[r], s2[r]);
#pragma unroll
            for (int o = 16; o > 0; o >>= 1)
                mt = fmaxf(mt, __shfl_xor_sync(0xffffffffu, mt, o));
            const float mnew = fmaxf(mrow[r], mt);
            const float resc = __expf(mrow[r] - mnew);
            p1[r] = __expf(s1[r] - mnew);
            p2[r] = __expf(s2[r] - mnew);
            float ps = p1[r] + p2[r];
#pragma unroll
            for (int o = 16; o > 0; o >>= 1)
                ps += __shfl_xor_sync(0xffffffffu, ps, o);
            lrow[r] = lrow[r] * resc + ps;
            mrow[r] = mnew;
            acc[r][0] *= resc;
            acc[r][1] *= resc;
        }

        __syncthreads();

#pragma unroll
        for (int r = 0; r < 8; r++) {
            sKP[(r0 + r) * 64 + c1] = p1[r];
            sKP[(r0 + r) * 64 + c2] = p2[r];
        }
        __syncwarp();

#pragma unroll
        for (int c4 = 0; c4 < BN; c4 += 4) {
            float v1[4], v2[4];
#pragma unroll
            for (int u = 0; u < 4; u++) {
                v1[u] = sV[(c4 + u) * 64 + c1];
                v2[u] = sV[(c4 + u) * 64 + c2];
            }
#pragma unroll
            for (int r = 0; r < 8; r++) {
                float4 pv = *(const float4*)&sKP[(r0 + r) * 64 + c4];
                acc[r][0] = fmaf(pv.x, v1[0], fmaf(pv.y, v1[1], fmaf(pv.z, v1[2], fmaf(pv.w, v1[3], acc[r][0]))));
                acc[r][1] = fmaf(pv.x, v2[0], fmaf(pv.y, v2[1], fmaf(pv.z, v2[2], fmaf(pv.w, v2[3], acc[r][1]))));
            }
        }
    }

    float* cb = g_ctx + (size_t)b * T * D + (size_t)h * HD;
#pragma unroll
    for (int r = 0; r < 8; r++) {
        const float inv = 1.0f / lrow[r];
        const int t = q0 + r0 + r;
        cb[(size_t)t * D + c1] = acc[r][0] * inv;
        cb[(size_t)t * D + c2] = acc[r][1] * inv;
    }
}

// ---------------------------------------------------------------------------
// Launch
// ---------------------------------------------------------------------------
extern "C" void kernel_launch(void* const* d_in, const int* in_sizes, int n_in,
                              void* d_out, int out_size)
{
    const float* x  = (const float*)d_in[0];
    const float* Wq = (const float*)d_in[1];
    const float* bq = (const float*)d_in[2];
    const float* Wk = (const float*)d_in[3];
    const float* bk = (const float*)d_in[4];
    const float* Wv = (const float*)d_in[5];
    const float* bv = (const float*)d_in[6];
    const float* Wo = (const float*)d_in[7];
    const float* bo = (const float*)d_in[8];

    cudaFuncSetAttribute(gemm_mma<0>, cudaFuncAttributeMaxDynamicSharedMemorySize, SMEM_DYN);
    cudaFuncSetAttribute(gemm_mma<1>, cudaFuncAttributeMaxDynamicSharedMemorySize, SMEM_DYN);
    cudaFuncSetAttribute(gemm_mma<2>, cudaFuncAttributeMaxDynamicSharedMemorySize, SMEM_DYN);
    cudaFuncSetAttribute(gemm_mma<3>, cudaFuncAttributeMaxDynamicSharedMemorySize, SMEM_DYN);

    const int n4x = M * K / 4;
    const int n4w = N * K / 4;

    split_k<0><<<(n4x + 255) / 256, 256>>>(x,  n4x);
    split_k<1><<<(n4w + 255) / 256, 256>>>(Wq, n4w);
    split_k<2><<<(n4w + 255) / 256, 256>>>(Wk, n4w);
    split_k<3><<<(n4w + 255) / 256, 256>>>(Wv, n4w);
    split_k<4><<<(n4w + 255) / 256, 256>>>(Wo, n4w);

    dim3 gg(N / 128, M / 128);   // (16, 32)
    gemm_mma<0><<<gg, 256, SMEM_DYN>>>(bq, nullptr);
    gemm_mma<1><<<gg, 256, SMEM_DYN>>>(bk, nullptr);
    gemm_mma<2><<<gg, 256, SMEM_DYN>>>(bv, nullptr);

    attn_kernel<<<dim3(T / BM, B * H), 256>>>();

    split_k<5><<<(n4x + 255) / 256, 256>>>(nullptr, n4x);
    gemm_mma<3><<<gg, 256, SMEM_DYN>>>(bo, (float*)d_out);
}

// round 6
// speedup vs baseline: 3.2938x; 1.5930x over previous
#include <cuda_runtime.h>
#include <cuda_bf16.h>
#include <math_constants.h>
#include <cstdint>

// Problem constants
constexpr int B  = 2;
constexpr int T  = 2048;
constexpr int D  = 2048;
constexpr int H  = 32;
constexpr int HD = 64;
constexpr int M  = B * T;      // 4096
constexpr int N  = D;          // 2048
constexpr int K  = D;          // 2048

// ---------------------------------------------------------------------------
// Device-global scratch (allocation-free rule). All bf16 hi/lo pairs.
// ---------------------------------------------------------------------------
__device__ __nv_bfloat16 g_xhi[(size_t)M * K];
__device__ __nv_bfloat16 g_xlo[(size_t)M * K];
__device__ __nv_bfloat16 g_chi[(size_t)M * K];
__device__ __nv_bfloat16 g_clo[(size_t)M * K];
__device__ __nv_bfloat16 g_whi[4][(size_t)N * K];
__device__ __nv_bfloat16 g_wlo[4][(size_t)N * K];

__device__ __nv_bfloat16 g_qhi[(size_t)B * H * T * HD];
__device__ __nv_bfloat16 g_qlo[(size_t)B * H * T * HD];
__device__ __nv_bfloat16 g_khi[(size_t)B * H * T * HD];
__device__ __nv_bfloat16 g_klo[(size_t)B * H * T * HD];
__device__ __nv_bfloat16 g_vhi[(size_t)B * H * T * HD];
__device__ __nv_bfloat16 g_vlo[(size_t)B * H * T * HD];

// ---------------------------------------------------------------------------
// PTX helpers (baseline sm_80/sm_90 features only — harness targets sm_100)
// ---------------------------------------------------------------------------
__device__ __forceinline__ uint32_t smem_u32(const void* p) {
    uint32_t a;
    asm("{ .reg .u64 t; cvta.to.shared.u64 t, %1; cvt.u32.u64 %0, t; }"
        : "=r"(a) : "l"(p));
    return a;
}

__device__ __forceinline__ void cp16(uint32_t d, const void* s) {
    asm volatile("cp.async.cg.shared.global [%0], [%1], 16;" :: "r"(d), "l"(s));
}
__device__ __forceinline__ void cp_commit()   { asm volatile("cp.async.commit_group;"); }
__device__ __forceinline__ void cp_wait1()    { asm volatile("cp.async.wait_group 1;"); }
__device__ __forceinline__ void cp_wait_all() { asm volatile("cp.async.wait_all;"); }

__device__ __forceinline__ void ldsm4(uint32_t* r, uint32_t addr) {
    asm volatile("ldmatrix.sync.aligned.m8n8.x4.shared.b16 {%0,%1,%2,%3}, [%4];"
                 : "=r"(r[0]), "=r"(r[1]), "=r"(r[2]), "=r"(r[3]) : "r"(addr));
}
__device__ __forceinline__ void ldsm4t(uint32_t* r, uint32_t addr) {
    asm volatile("ldmatrix.sync.aligned.m8n8.x4.trans.shared.b16 {%0,%1,%2,%3}, [%4];"
                 : "=r"(r[0]), "=r"(r[1]), "=r"(r[2]), "=r"(r[3]) : "r"(addr));
}

__device__ __forceinline__ void mma16816(float* c, const uint32_t* a,
                                         const uint32_t* b) {
    asm volatile(
        "mma.sync.aligned.m16n8k16.row.col.f32.bf16.bf16.f32 "
        "{%0,%1,%2,%3}, {%4,%5,%6,%7}, {%8,%9}, {%0,%1,%2,%3};"
        : "+f"(c[0]), "+f"(c[1]), "+f"(c[2]), "+f"(c[3])
        : "r"(a[0]), "r"(a[1]), "r"(a[2]), "r"(a[3]), "r"(b[0]), "r"(b[1]));
}

// SW128 swizzle: byte offset within a [rows x 128B] tile
__device__ __forceinline__ uint32_t swz(int row, int col_bf16) {
    return (uint32_t)(row * 128 + ((((col_bf16 >> 3) ^ row) & 7) << 4) +
                      (col_bf16 & 7) * 2);
}

// fp32 pair -> bf16 hi/lo packed words
__device__ __forceinline__ void hilo2(float x, float y, uint32_t& hi, uint32_t& lo) {
    __nv_bfloat16 hx = __float2bfloat16(x), hy = __float2bfloat16(y);
    __nv_bfloat16 lx = __float2bfloat16(x - __bfloat162float(hx));
    __nv_bfloat16 ly = __float2bfloat16(y - __bfloat162float(hy));
    __nv_bfloat162 ph(hx, hy), pl(lx, ly);
    hi = *(uint32_t*)&ph;
    lo = *(uint32_t*)&pl;
}

// ---------------------------------------------------------------------------
// Split fp32 -> bf16 hi/lo.  DST: 0=x, 1..4=W[DST-1]
// ---------------------------------------------------------------------------
template<int DST>
__global__ __launch_bounds__(256)
void split_k(const float* __restrict__ src, int n4)
{
    const int i = blockIdx.x * blockDim.x + threadIdx.x;
    if (i >= n4) return;
    __nv_bfloat16* hp = (DST == 0) ? g_xhi : g_whi[DST-1];
    __nv_bfloat16* lp = (DST == 0) ? g_xlo : g_wlo[DST-1];

    float4 v = ((const float4*)src)[i];
    uint32_t h0, l0, h1, l1;
    hilo2(v.x, v.y, h0, l0);
    hilo2(v.z, v.w, h1, l1);
    uint32_t* hp2 = (uint32_t*)hp;
    uint32_t* lp2 = (uint32_t*)lp;
    hp2[2*i] = h0; hp2[2*i+1] = h1;
    lp2[2*i] = l0; lp2[2*i+1] = l1;
}

// ---------------------------------------------------------------------------
// HMMA GEMM: out = A @ W^T + bias, bf16 hi+lo, 3-term compensation.
// CTA 128x128, KC=64, cp.async double buffer, 8 warps (2x4), warp tile 64x32.
// MODE 0/1/2: epilogue -> bf16 hi/lo q/k/v [B,H,T,HD]. MODE 3: fp32 flat out.
// ---------------------------------------------------------------------------
constexpr int KC    = 64;
constexpr int NSTG  = K / KC;             // 32
constexpr int TILEB = 128 * 128;          // 16 KB per operand tile
constexpr int STGB  = 4 * TILEB;          // 64 KB per stage
constexpr int SMEM_DYN = 2 * STGB;        // 128 KB

template<int MODE>
__global__ __launch_bounds__(256, 1)
void gemm_mma(const float* __restrict__ bias, float* __restrict__ out_p)
{
    extern __shared__ char smem[];
    const uint32_t sb = smem_u32(smem);
    const int tid  = threadIdx.x;
    const int warp = tid >> 5;
    const int lane = tid & 31;
    const int m0 = blockIdx.y * 128;
    const int n0 = blockIdx.x * 128;

    const __nv_bfloat16* Ahi = (MODE < 3) ? g_xhi : g_chi;
    const __nv_bfloat16* Alo = (MODE < 3) ? g_xlo : g_clo;
    const __nv_bfloat16* Bhi = g_whi[MODE < 3 ? MODE : 3];
    const __nv_bfloat16* Blo = g_wlo[MODE < 3 ? MODE : 3];

    const int wm = (warp >> 2) * 64;   // warp M base (0 or 64)
    const int wn = (warp & 3) * 32;    // warp N base

    float acc[4][4][4];
#pragma unroll
    for (int i = 0; i < 4; i++)
#pragma unroll
        for (int j = 0; j < 4; j++)
#pragma unroll
            for (int r = 0; r < 4; r++) acc[i][j][r] = 0.0f;

    auto issue_load = [&](int s) {
        const int k0 = s * KC;
        const uint32_t buf = sb + (s & 1) * STGB;
#pragma unroll
        for (int i = 0; i < 4; i++) {
            const int idx = tid + i * 256;       // 0..1023
            const int row = idx >> 3;            // 0..127
            const int ch  = idx & 7;             // 16B chunk
            const uint32_t off = row * 128 + (((ch ^ row) & 7) << 4);
            const size_t gA = (size_t)(m0 + row) * K + k0 + ch * 8;
            const size_t gB = (size_t)(n0 + row) * K + k0 + ch * 8;
            cp16(buf + 0 * TILEB + off, Ahi + gA);
            cp16(buf + 1 * TILEB + off, Alo + gA);
            cp16(buf + 2 * TILEB + off, Bhi + gB);
            cp16(buf + 3 * TILEB + off, Blo + gB);
        }
    };

    issue_load(0); cp_commit();
    issue_load(1); cp_commit();

    const int a_r = (lane & 7) + ((lane >> 3) & 1) * 8;   // m within 16
    const int a_c = ((lane >> 4) & 1) * 8;                // k within 16
    const int b_r = (lane & 7) + ((lane >> 4) & 1) * 8;   // n within 16
    const int b_c = ((lane >> 3) & 1) * 8;                // k within 16

    for (int s = 0; s < NSTG; s++) {
        cp_wait1();
        __syncthreads();
        const uint32_t buf = sb + (s & 1) * STGB;
        const uint32_t sAh = buf, sAl = buf + TILEB;
        const uint32_t sBh = buf + 2 * TILEB, sBl = buf + 3 * TILEB;

#pragma unroll
        for (int kk = 0; kk < 4; kk++) {
            const int kc = kk * 16;
            uint32_t ah[4][4], al[4][4], bh[2][4], bl[2][4];
#pragma unroll
            for (int mt = 0; mt < 4; mt++) {
                const uint32_t off = swz(wm + mt * 16 + a_r, kc + a_c);
                ldsm4(ah[mt], sAh + off);
                ldsm4(al[mt], sAl + off);
            }
#pragma unroll
            for (int np = 0; np < 2; np++) {
                const uint32_t off = swz(wn + np * 16 + b_r, kc + b_c);
                ldsm4(bh[np], sBh + off);
                ldsm4(bl[np], sBl + off);
            }
#pragma unroll
            for (int mt = 0; mt < 4; mt++)
#pragma unroll
                for (int nt = 0; nt < 4; nt++) {
                    const int np = nt >> 1, hb = (nt & 1) * 2;
                    mma16816(acc[mt][nt], ah[mt], &bh[np][hb]);
                    mma16816(acc[mt][nt], ah[mt], &bl[np][hb]);
                    mma16816(acc[mt][nt], al[mt], &bh[np][hb]);
                }
        }
        __syncthreads();
        if (s + 2 < NSTG) issue_load(s + 2);
        cp_commit();
    }
    cp_wait_all();

    // ---- epilogue ----
    const int qr = lane >> 2;          // 0..7
    const int qc = (lane & 3) * 2;     // 0,2,4,6

    __nv_bfloat16* dhi = (MODE == 0) ? g_qhi : (MODE == 1) ? g_khi : g_vhi;
    __nv_bfloat16* dlo = (MODE == 0) ? g_qlo : (MODE == 1) ? g_klo : g_vlo;

#pragma unroll
    for (int mt = 0; mt < 4; mt++) {
#pragma unroll
        for (int nt = 0; nt < 4; nt++) {
            const int n  = n0 + wn + nt * 8 + qc;
            const float2 bb = *(const float2*)&bias[n];
            const int m_lo = m0 + wm + mt * 16 + qr;
            const int m_hi = m_lo + 8;

            float2 v0 = make_float2(acc[mt][nt][0] + bb.x, acc[mt][nt][1] + bb.y);
            float2 v1 = make_float2(acc[mt][nt][2] + bb.x, acc[mt][nt][3] + bb.y);

            if (MODE == 3) {
                *(float2*)&out_p[(size_t)m_lo * N + n] = v0;
                *(float2*)&out_p[(size_t)m_hi * N + n] = v1;
            } else {
                const int h  = n >> 6;
                const int hd = n & 63;
                const int b_lo = m_lo >> 11, t_lo = m_lo & (T - 1);
                const int b_hi = m_hi >> 11, t_hi = m_hi & (T - 1);
                const size_t o0 = ((size_t)(b_lo * H + h) * T + t_lo) * HD + hd;
                const size_t o1 = ((size_t)(b_hi * H + h) * T + t_hi) * HD + hd;
                uint32_t h0, l0, h1, l1;
                hilo2(v0.x, v0.y, h0, l0);
                hilo2(v1.x, v1.y, h1, l1);
                *(uint32_t*)&dhi[o0] = h0; *(uint32_t*)&dlo[o0] = l0;
                *(uint32_t*)&dhi[o1] = h1; *(uint32_t*)&dlo[o1] = l1;
            }
        }
    }
}

// ---------------------------------------------------------------------------
// Flash attention on HMMA (causal). BM=128 (8 warps x m16), BN=64, HD=64.
// S = Q K^T via 3-term bf16 compensation; softmax in registers; P repacked
// C-frag -> A-frag, split hi/lo; O += P V with V via ldmatrix.trans (3 terms).
// Epilogue writes ctx directly as bf16 hi/lo (feeds MODE 3 GEMM).
// ---------------------------------------------------------------------------
constexpr int ABM = 128;
constexpr int ABN = 64;
constexpr int AQB  = 128 * 128;            // 16 KB per Q array
constexpr int AKVT = 64 * 128;             // 8 KB per K/V tile
constexpr int ASTG = 4 * AKVT;             // 32 KB per stage
constexpr int ASMEM = 2 * AQB + 2 * ASTG;  // 96 KB

__global__ __launch_bounds__(256, 1)
void attn_mma()
{
    extern __shared__ char smem[];
    const uint32_t sb = smem_u32(smem);
    const int tid  = threadIdx.x;
    const int warp = tid >> 5;
    const int lane = tid & 31;
    const int bh   = blockIdx.y;           // 0..63
    const int b    = bh >> 5;
    const int h    = bh & (H - 1);
    const int q0   = blockIdx.x * ABM;

    const __nv_bfloat16* qhb = g_qhi + (size_t)bh * T * HD;
    const __nv_bfloat16* qlb = g_qlo + (size_t)bh * T * HD;
    const __nv_bfloat16* khb = g_khi + (size_t)bh * T * HD;
    const __nv_bfloat16* klb = g_klo + (size_t)bh * T * HD;
    const __nv_bfloat16* vhb = g_vhi + (size_t)bh * T * HD;
    const __nv_bfloat16* vlb = g_vlo + (size_t)bh * T * HD;

    const int ntiles = q0 / ABN + 2;       // causal: tiles j0=0..q0+64

    // ---- Q load (group 0 with KV tile 0) ----
#pragma unroll
    for (int i = 0; i < 4; i++) {
        const int idx = tid + i * 256;     // 0..1023
        const int row = idx >> 3;
        const int ch  = idx & 7;
        const uint32_t off = row * 128 + (((ch ^ row) & 7) << 4);
        const size_t g = (size_t)(q0 + row) * HD + ch * 8;
        cp16(sb + off,        qhb + g);
        cp16(sb + AQB + off,  qlb + g);
    }

    auto kv_load = [&](int it) {
        const uint32_t buf = sb + 2 * AQB + (it & 1) * ASTG;
        const int j0 = it * ABN;
#pragma unroll
        for (int i = 0; i < 2; i++) {
            const int idx = tid + i * 256;  // 0..511
            const int row = idx >> 3;       // 0..63
            const int ch  = idx & 7;
            const uint32_t off = row * 128 + (((ch ^ row) & 7) << 4);
            const size_t g = (size_t)(j0 + row) * HD + ch * 8;
            cp16(buf + 0 * AKVT + off, khb + g);
            cp16(buf + 1 * AKVT + off, klb + g);
            cp16(buf + 2 * AKVT + off, vhb + g);
            cp16(buf + 3 * AKVT + off, vlb + g);
        }
    };

    kv_load(0); cp_commit();
    if (ntiles > 1) kv_load(1);
    cp_commit();

    // fragment lane mappings
    const int a_r = (lane & 7) + ((lane >> 3) & 1) * 8;   // m within 16
    const int a_c = ((lane >> 4) & 1) * 8;                // k within 16
    const int b_r = (lane & 7) + ((lane >> 4) & 1) * 8;   // n within 16
    const int b_c = ((lane >> 3) & 1) * 8;                // k within 16
    const int v_r = (lane & 7) + ((lane >> 3) & 1) * 8;   // key row within 16
    const int v_c = ((lane >> 4) & 1) * 8;                // hd col within 16

    const int row_a = q0 + warp * 16 + (lane >> 2);       // global query row
    const int row_b = row_a + 8;
    const int wrow_max = q0 + warp * 16 + 15;

    float oacc[8][4];
#pragma unroll
    for (int i = 0; i < 8; i++)
#pragma unroll
        for (int r = 0; r < 4; r++) oacc[i][r] = 0.0f;
    float m_a = -1e30f, m_b = -1e30f, l_a = 0.0f, l_b = 0.0f;

    for (int it = 0; it < ntiles; it++) {
        cp_wait1();
        __syncthreads();
        const uint32_t buf = sb + 2 * AQB + (it & 1) * ASTG;
        const uint32_t sKh = buf, sKl = buf + AKVT;
        const uint32_t sVh = buf + 2 * AKVT, sVl = buf + 3 * AKVT;
        const int j0 = it * ABN;

        if (j0 <= wrow_max) {   // not fully masked for this warp
            // ---- S = Q K^T (3 terms) ----
            float sc[8][4];
#pragma unroll
            for (int i = 0; i < 8; i++)
#pragma unroll
                for (int r = 0; r < 4; r++) sc[i][r] = 0.0f;

#pragma unroll
            for (int kb = 0; kb < 4; kb++) {
                const int kc = kb * 16;
                uint32_t qh[4], ql[4];
                const uint32_t offq = swz(warp * 16 + a_r, kc + a_c);
                ldsm4(qh, sb + offq);
                ldsm4(ql, sb + AQB + offq);
#pragma unroll
                for (int np = 0; np < 4; np++) {
                    uint32_t kh[4], kl[4];
                    const uint32_t offb = swz(np * 16 + b_r, kc + b_c);
                    ldsm4(kh, sKh + offb);
                    ldsm4(kl, sKl + offb);
#pragma unroll
                    for (int h2 = 0; h2 < 2; h2++) {
                        const int nt = np * 2 + h2, hb = h2 * 2;
                        mma16816(sc[nt], qh, &kh[hb]);
                        mma16816(sc[nt], qh, &kl[hb]);
                        mma16816(sc[nt], ql, &kh[hb]);
                    }
                }
            }

            // ---- scale + causal mask ----
#pragma unroll
            for (int nt = 0; nt < 8; nt++) {
#pragma unroll
                for (int e = 0; e < 2; e++) {
                    const int key = j0 + nt * 8 + (lane & 3) * 2 + e;
                    sc[nt][e]     = (key <= row_a) ? sc[nt][e]     * 0.125f : -1e30f;
                    sc[nt][2 + e] = (key <= row_b) ? sc[nt][2 + e] * 0.125f : -1e30f;
                }
            }

            // ---- online softmax ----
            float ma = -1e30f, mb = -1e30f;
#pragma unroll
            for (int nt = 0; nt < 8; nt++) {
                ma = fmaxf(ma, fmaxf(sc[nt][0], sc[nt][1]));
                mb = fmaxf(mb, fmaxf(sc[nt][2], sc[nt][3]));
            }
            ma = fmaxf(ma, __shfl_xor_sync(0xffffffffu, ma, 1));
            ma = fmaxf(ma, __shfl_xor_sync(0xffffffffu, ma, 2));
            mb = fmaxf(mb, __shfl_xor_sync(0xffffffffu, mb, 1));
            mb = fmaxf(mb, __shfl_xor_sync(0xffffffffu, mb, 2));

            const float mna = fmaxf(m_a, ma), mnb = fmaxf(m_b, mb);
            const float ra = __expf(m_a - mna), rb = __expf(m_b - mnb);
            m_a = mna; m_b = mnb;

            float suma = 0.0f, sumb = 0.0f;
#pragma unroll
            for (int nt = 0; nt < 8; nt++) {
                sc[nt][0] = __expf(sc[nt][0] - mna);
                sc[nt][1] = __expf(sc[nt][1] - mna);
                sc[nt][2] = __expf(sc[nt][2] - mnb);
                sc[nt][3] = __expf(sc[nt][3] - mnb);
                suma += sc[nt][0] + sc[nt][1];
                sumb += sc[nt][2] + sc[nt][3];
            }
            suma += __shfl_xor_sync(0xffffffffu, suma, 1);
            suma += __shfl_xor_sync(0xffffffffu, suma, 2);
            sumb += __shfl_xor_sync(0xffffffffu, sumb, 1);
            sumb += __shfl_xor_sync(0xffffffffu, sumb, 2);
            l_a = l_a * ra + suma;
            l_b = l_b * rb + sumb;

#pragma unroll
            for (int nt = 0; nt < 8; nt++) {
                oacc[nt][0] *= ra; oacc[nt][1] *= ra;
                oacc[nt][2] *= rb; oacc[nt][3] *= rb;
            }

            // ---- O += P V (3 terms), P from accum frags ----
#pragma unroll
            for (int kb = 0; kb < 4; kb++) {
                const int t0 = 2 * kb, t1 = 2 * kb + 1;
                uint32_t pah[4], pal[4];
                hilo2(sc[t0][0], sc[t0][1], pah[0], pal[0]);
                hilo2(sc[t0][2], sc[t0][3], pah[1], pal[1]);
                hilo2(sc[t1][0], sc[t1][1], pah[2], pal[2]);
                hilo2(sc[t1][2], sc[t1][3], pah[3], pal[3]);
#pragma unroll
                for (int np = 0; np < 4; np++) {
                    uint32_t vh[4], vl[4];
                    const uint32_t offv = swz(kb * 16 + v_r, np * 16 + v_c);
                    ldsm4t(vh, sVh + offv);
                    ldsm4t(vl, sVl + offv);
#pragma unroll
                    for (int h2 = 0; h2 < 2; h2++) {
                        const int nt = np * 2 + h2, hb = h2 * 2;
                        mma16816(oacc[nt], pah, &vh[hb]);
                        mma16816(oacc[nt], pah, &vl[hb]);
                        mma16816(oacc[nt], pal, &vh[hb]);
                    }
                }
            }
        }

        __syncthreads();
        if (it + 2 < ntiles) kv_load(it + 2);
        cp_commit();
    }
    cp_wait_all();

    // ---- epilogue: normalize, write ctx bf16 hi/lo ----
    const float inva = 1.0f / l_a, invb = 1.0f / l_b;
    const size_t mr_a = (size_t)(b * T + (row_a - q0) + q0) * D;  // row_a global
    const size_t mr_b = mr_a + 8 * D;
    const int colb = h * 64 + (lane & 3) * 2;
#pragma unroll
    for (int nt = 0; nt < 8; nt++) {
        const size_t ia = mr_a + colb + nt * 8;
        const size_t ib = mr_b + colb + nt * 8;
        uint32_t hA, lA, hB, lB;
        hilo2(oacc[nt][0] * inva, oacc[nt][1] * inva, hA, lA);
        hilo2(oacc[nt][2] * invb, oacc[nt][3] * invb, hB, lB);
        *(uint32_t*)&g_chi[ia] = hA; *(uint32_t*)&g_clo[ia] = lA;
        *(uint32_t*)&g_chi[ib] = hB; *(uint32_t*)&g_clo[ib] = lB;
    }
}

// ---------------------------------------------------------------------------
// Launch
// ---------------------------------------------------------------------------
extern "C" void kernel_launch(void* const* d_in, const int* in_sizes, int n_in,
                              void* d_out, int out_size)
{
    const float* x  = (const float*)d_in[0];
    const float* Wq = (const float*)d_in[1];
    const float* bq = (const float*)d_in[2];
    const float* Wk = (const float*)d_in[3];
    const float* bk = (const float*)d_in[4];
    const float* Wv = (const float*)d_in[5];
    const float* bv = (const float*)d_in[6];
    const float* Wo = (const float*)d_in[7];
    const float* bo = (const float*)d_in[8];

    cudaFuncSetAttribute(gemm_mma<0>, cudaFuncAttributeMaxDynamicSharedMemorySize, SMEM_DYN);
    cudaFuncSetAttribute(gemm_mma<1>, cudaFuncAttributeMaxDynamicSharedMemorySize, SMEM_DYN);
    cudaFuncSetAttribute(gemm_mma<2>, cudaFuncAttributeMaxDynamicSharedMemorySize, SMEM_DYN);
    cudaFuncSetAttribute(gemm_mma<3>, cudaFuncAttributeMaxDynamicSharedMemorySize, SMEM_DYN);
    cudaFuncSetAttribute(attn_mma,    cudaFuncAttributeMaxDynamicSharedMemorySize, ASMEM);

    const int n4x = M * K / 4;
    const int n4w = N * K / 4;

    split_k<0><<<(n4x + 255) / 256, 256>>>(x,  n4x);
    split_k<1><<<(n4w + 255) / 256, 256>>>(Wq, n4w);
    split_k<2><<<(n4w + 255) / 256, 256>>>(Wk, n4w);
    split_k<3><<<(n4w + 255) / 256, 256>>>(Wv, n4w);
    split_k<4><<<(n4w + 255) / 256, 256>>>(Wo, n4w);

    dim3 gg(N / 128, M / 128);   // (16, 32)
    gemm_mma<0><<<gg, 256, SMEM_DYN>>>(bq, nullptr);
    gemm_mma<1><<<gg, 256, SMEM_DYN>>>(bk, nullptr);
    gemm_mma<2><<<gg, 256, SMEM_DYN>>>(bv, nullptr);

    attn_mma<<<dim3(T / ABM, B * H), 256, ASMEM>>>();

    gemm_mma<3><<<gg, 256, SMEM_DYN>>>(bo, (float*)d_out);
}